// round 15
// baseline (speedup 1.0000x reference)
#include <cuda_runtime.h>
#include <cuda_bf16.h>

#define BB 16
#define SS 1024
#define CO 88
#define QSCALE 0.31622776601683794f
#define L2E 1.4426950408889634f
#define SCL (QSCALE * L2E)

typedef unsigned int uint32;

__device__ __forceinline__ float ex2f(float x) {
    float r; asm("ex2.approx.ftz.f32 %0, %1;" : "=f"(r) : "f"(x)); return r;
}
__device__ __forceinline__ uint32 pkbf(float hi, float lo) {
    uint32 r; asm("cvt.rn.bf16x2.f32 %0, %1, %2;" : "=r"(r) : "f"(hi), "f"(lo)); return r;
}
__device__ __forceinline__ uint32 f2tf(float x) {
    uint32 r; asm("cvt.rna.tf32.f32 %0, %1;" : "=r"(r) : "f"(x)); return r;
}
__device__ __forceinline__ float lo_bf(uint32 p) { return __uint_as_float(p << 16); }
__device__ __forceinline__ float hi_bf(uint32 p) { return __uint_as_float(p & 0xffff0000u); }
#define MMA16(d, a, b) asm volatile( \
    "mma.sync.aligned.m16n8k16.row.col.f32.bf16.bf16.f32 " \
    "{%0,%1,%2,%3}, {%4,%5,%6,%7}, {%8,%9}, {%0,%1,%2,%3};\n" \
    : "+f"(d[0]), "+f"(d[1]), "+f"(d[2]), "+f"(d[3]) \
    : "r"(a[0]), "r"(a[1]), "r"(a[2]), "r"(a[3]), "r"(b[0]), "r"(b[1]))
#define MMAT(d, a, b) asm volatile( \
    "mma.sync.aligned.m16n8k8.row.col.f32.tf32.tf32.f32 " \
    "{%0,%1,%2,%3}, {%4,%5,%6,%7}, {%8,%9}, {%0,%1,%2,%3};\n" \
    : "+f"(d[0]), "+f"(d[1]), "+f"(d[2]), "+f"(d[3]) \
    : "r"(a[0]), "r"(a[1]), "r"(a[2]), "r"(a[3]), "r"(b[0]), "r"(b[1]))

// ---------------- scratch ----------------
__device__ float g_h[BB * 64 * SS];
__device__ float g_part[BB * 64 * 2];
__device__ float g_conv[BB * CO * SS];
__device__ float g_qkv[BB * 120 * SS];
__device__ float g_attn[BB * 4 * SS * 10];
__device__ float g_apart[2 * 64 * 1024 * 12];   // [ks][bh*1024][12]: 10 O cols + s
__device__ uint32 g_wco[4 * 9 * 88 * 16];
__device__ uint32 g_wq[120 * 64];

// ---------------- BN scale/shift recompute (inline per block) ----------------
__device__ __forceinline__ void bn_inline(float* bns, float* bnb,
                                          const float* __restrict__ gma,
                                          const float* __restrict__ bet, int tid) {
    if (tid < 64) {
        float S = 0.f, S2 = 0.f;
#pragma unroll
        for (int ib = 0; ib < 16; ib++) {
            S  += g_part[(ib * 64 + tid) * 2];
            S2 += g_part[(ib * 64 + tid) * 2 + 1];
        }
        float mu  = S * (1.f / 16384.f);
        float var = S2 * (1.f / 16384.f) - mu * mu;
        float sc = gma[tid] * rsqrtf(var + 1e-5f);
        bns[tid] = sc;
        bnb[tid] = bet[tid] - mu * sc;
    }
}

// ---------------- conv1 3->64 3x3 + BN partial stats + weight prep ----------------
__global__ void conv1_kernel(const float* __restrict__ x, const float* __restrict__ w,
                             const float* __restrict__ bias,
                             const float* __restrict__ convo_w,
                             const float* __restrict__ qkv_w) {
    int oc = blockIdx.x, b = blockIdx.y;
    __shared__ float xs[3 * 34 * 34];
    __shared__ float ws[27];
    __shared__ float sred[16];
    int tid = threadIdx.x;
    if (b == 0) {
        int base = oc * 256 + tid;
        for (int i = base; i < 4 * 9 * 88 * 16; i += 16384) {
            int ic16 = i & 15, r = i >> 4;
            int occ = r % 88; r /= 88;
            int kk = r % 9;  int icc = r / 9;
            g_wco[i] = f2tf(convo_w[(occ * 64 + icc * 16 + ic16) * 9 + kk]);
        }
        for (int i = base; i < 120 * 64; i += 16384) g_wq[i] = f2tf(qkv_w[i]);
    }
    for (int i = tid; i < 3 * 1156; i += 256) {
        int ic = i / 1156, r = i % 1156;
        int y = r / 34 - 1, xx = r % 34 - 1;
        float v = 0.f;
        if ((unsigned)y < 32u && (unsigned)xx < 32u)
            v = x[(b * 3 + ic) * SS + y * 32 + xx];
        xs[i] = v;
    }
    if (tid < 27) ws[tid] = w[oc * 27 + tid];
    __syncthreads();
    float bb = bias[oc];
    float s = 0.f, s2 = 0.f;
    for (int p = tid; p < SS; p += 256) {
        int y = p >> 5, xx = p & 31;
        float acc = bb;
#pragma unroll
        for (int ic = 0; ic < 3; ic++)
#pragma unroll
            for (int ky = 0; ky < 3; ky++)
#pragma unroll
                for (int kx = 0; kx < 3; kx++)
                    acc += xs[ic * 1156 + (y + ky) * 34 + xx + kx] * ws[ic * 9 + ky * 3 + kx];
        g_h[(b * 64 + oc) * SS + p] = acc;
        s += acc; s2 += acc * acc;
    }
#pragma unroll
    for (int o = 16; o; o >>= 1) {
        s  += __shfl_xor_sync(0xffffffffu, s, o);
        s2 += __shfl_xor_sync(0xffffffffu, s2, o);
    }
    if ((tid & 31) == 0) { sred[tid >> 5] = s; sred[8 + (tid >> 5)] = s2; }
    __syncthreads();
    if (tid == 0) {
        float S = 0.f, S2 = 0.f;
        for (int i = 0; i < 8; i++) { S += sred[i]; S2 += sred[8 + i]; }
        g_part[(b * 64 + oc) * 2]     = S;
        g_part[(b * 64 + oc) * 2 + 1] = S2;
    }
}

// ---------------- convo: tf32 implicit-GEMM, oc-split (48 + 40) ----------------
#define CONVO_SMEM ((6 * 36 * 18 + 9 * 48 * 18 + 48) * 4)
template <int NT, int OCB>
__device__ __forceinline__ void convo_impl(const float* __restrict__ bias,
                                           const float* __restrict__ gma,
                                           const float* __restrict__ bet) {
    extern __shared__ uint32 dynu[];
    uint32* xs = dynu;
    uint32* ws = xs + 6 * 36 * 18;
    float* bsm = (float*)(ws + 9 * 48 * 18);
    __shared__ float bns[64], bnb[64];
    int pxt = blockIdx.x, b = blockIdx.y;
    int y0 = pxt * 4;
    int tid = threadIdx.x;
    int wz = tid >> 5, lane = tid & 31;
    int g = lane >> 2, t = lane & 3;
    int wrow = wz >> 1, mtx = (wz & 1) * 16;

    bn_inline(bns, bnb, gma, bet, tid);
    if (tid < NT * 8) bsm[tid] = bias[OCB + tid];

    float acc[NT][4];
#pragma unroll
    for (int n = 0; n < NT; n++)
#pragma unroll
        for (int j = 0; j < 4; j++) acc[n][j] = 0.f;

    for (int icc = 0; icc < 4; icc++) {
        __syncthreads();
        for (int i = tid; i < 3456; i += 256) {
            int ic = i / 216, rem = i % 216;
            int row = rem / 36, col = rem % 36;
            int iy = y0 - 1 + row, ix = col - 1;
            float v = 0.f;
            int icg = icc * 16 + ic;
            if ((unsigned)iy < 32u && (unsigned)ix < 32u) {
                v = g_h[(b * 64 + icg) * SS + iy * 32 + ix];
                v = fmaxf(v * bns[icg] + bnb[icg], 0.f);
            }
            xs[(row * 36 + col) * 18 + ic] = f2tf(v);
        }
        for (int i = tid; i < 9 * NT * 8 * 16; i += 256) {
            int ic = i & 15, m = i >> 4;
            int ocl = m % (NT * 8), kk = m / (NT * 8);
            ws[(kk * 48 + ocl) * 18 + ic] = g_wco[((icc * 9 + kk) * 88 + OCB + ocl) * 16 + ic];
        }
        __syncthreads();
#pragma unroll
        for (int kk = 0; kk < 9; kk++) {
            int ky = kk / 3, kx = kk % 3;
            const uint32* xrow = xs + ((wrow + ky) * 36 + mtx + kx) * 18;
            const uint32* wrow_p = ws + kk * 48 * 18;
#pragma unroll
            for (int j = 0; j < 2; j++) {
                uint32 a[4];
                a[0] = xrow[g * 18 + 8 * j + t];
                a[1] = xrow[(g + 8) * 18 + 8 * j + t];
                a[2] = xrow[g * 18 + 8 * j + t + 4];
                a[3] = xrow[(g + 8) * 18 + 8 * j + t + 4];
#pragma unroll
                for (int nt = 0; nt < NT; nt++) {
                    uint32 bfrag[2];
                    bfrag[0] = wrow_p[(nt * 8 + g) * 18 + 8 * j + t];
                    bfrag[1] = wrow_p[(nt * 8 + g) * 18 + 8 * j + t + 4];
                    MMAT(acc[nt], a, bfrag);
                }
            }
        }
    }
    int pxbase = (y0 + wrow) * 32 + mtx;
#pragma unroll
    for (int nt = 0; nt < NT; nt++) {
        int oc0 = OCB + nt * 8 + 2 * t;
        float b0 = bsm[nt * 8 + 2 * t], b1 = bsm[nt * 8 + 2 * t + 1];
        float* o0 = g_conv + (size_t)(b * 88 + oc0) * SS + pxbase;
        float* o1 = o0 + SS;
        o0[g]     = acc[nt][0] + b0;
        o1[g]     = acc[nt][1] + b1;
        o0[g + 8] = acc[nt][2] + b0;
        o1[g + 8] = acc[nt][3] + b1;
    }
}

__global__ void __launch_bounds__(256) convo_mma_kernel(const float* __restrict__ bias,
                                                        const float* __restrict__ gma,
                                                        const float* __restrict__ bet) {
    if (blockIdx.z == 0) convo_impl<6, 0>(bias, gma, bet);
    else                 convo_impl<5, 48>(bias, gma, bet);
}

// ---------------- qkv 1x1: tf32 MMA GEMM ----------------
#define QKV_SMEM ((128 * 68 + 120 * 68 + 120) * 4)
__global__ void __launch_bounds__(256) qkv_mma_kernel(const float* __restrict__ bias,
                                                      const float* __restrict__ gma,
                                                      const float* __restrict__ bet) {
    extern __shared__ uint32 dynu[];
    uint32* As = dynu;
    uint32* wqs = As + 128 * 68;
    float* bsm = (float*)(wqs + 120 * 68);
    __shared__ float bns[64], bnb[64];
    int pxt = blockIdx.x, b = blockIdx.y;
    int p0 = pxt * 128;
    int tid = threadIdx.x;
    int wz = tid >> 5, lane = tid & 31;
    int g = lane >> 2, t = lane & 3;

    bn_inline(bns, bnb, gma, bet, tid);
    for (int i = tid; i < 120; i += 256) bsm[i] = bias[i];
    for (int i = tid; i < 120 * 64; i += 256) {
        int n = i >> 6, ic = i & 63;
        wqs[n * 68 + ic] = g_wq[i];
    }
    __syncthreads();
    for (int i = tid; i < 128 * 64; i += 256) {
        int ic = i >> 7, px = i & 127;
        float v = g_h[(b * 64 + ic) * SS + p0 + px];
        v = fmaxf(v * bns[ic] + bnb[ic], 0.f);
        As[px * 68 + ic] = f2tf(v);
    }
    __syncthreads();

    float acc[15][4];
#pragma unroll
    for (int n = 0; n < 15; n++)
#pragma unroll
        for (int j = 0; j < 4; j++) acc[n][j] = 0.f;

#pragma unroll
    for (int kc = 0; kc < 8; kc++) {
        int ic0 = kc * 8;
        const uint32* ar = As + (wz * 16) * 68 + ic0;
        uint32 a[4];
        a[0] = ar[g * 68 + t];
        a[1] = ar[(g + 8) * 68 + t];
        a[2] = ar[g * 68 + t + 4];
        a[3] = ar[(g + 8) * 68 + t + 4];
#pragma unroll
        for (int nt = 0; nt < 15; nt++) {
            uint32 bfrag[2];
            bfrag[0] = wqs[(nt * 8 + g) * 68 + ic0 + t];
            bfrag[1] = wqs[(nt * 8 + g) * 68 + ic0 + t + 4];
            MMAT(acc[nt], a, bfrag);
        }
    }
    int pxb = p0 + wz * 16;
#pragma unroll
    for (int nt = 0; nt < 15; nt++) {
        int oc0 = nt * 8 + 2 * t;
        float b0 = bsm[oc0], b1 = bsm[oc0 + 1];
        float* o0 = g_qkv + (size_t)(b * 120 + oc0) * SS + pxb;
        float* o1 = o0 + SS;
        o0[g]     = acc[nt][0] + b0;
        o1[g]     = acc[nt][1] + b1;
        o0[g + 8] = acc[nt][2] + b0;
        o1[g + 8] = acc[nt][3] + b1;
    }
}

// ---------------- fused attention: split-K flash-style, 3 blocks/SM ----------------
// grid (4 qt, 64 bh, 2 ks); each block: 256 queries x 512 keys.
// smem: K[512][18]bf16 (18432) | V[16][260]u32 (16640) | RH[256][17]bf16 (8704) |
//       RWP[256][17]u32 (17408, persistent).  srel+Q overlay inside K/V region.
#define SM_K    0
#define SM_V    18432
#define SM_RH   35072
#define SM_RWP  43776
#define ATTN_SMEM 61184
#define OV_SREL 0
#define OV_Q    5056

__global__ void __launch_bounds__(256, 3) attn_kernel(const float* __restrict__ relh,
                                                      const float* __restrict__ relw) {
    extern __shared__ char smem[];
    __nv_bfloat16* Ksm = (__nv_bfloat16*)(smem + SM_K);   // [512][18]
    uint32* K32 = (uint32*)(smem + SM_K);                 // [512][9]
    uint32* V32 = (uint32*)(smem + SM_V);                 // [16][260]
    __nv_bfloat16* RH = (__nv_bfloat16*)(smem + SM_RH);   // [256][17] (16 used)
    uint32* RWP = (uint32*)(smem + SM_RWP);               // [256][17]
    float* srel = (float*)(smem + OV_SREL);               // overlay
    __nv_bfloat16* Qsm = (__nv_bfloat16*)(smem + OV_Q);   // overlay [256][16]
    uint32* Q32 = (uint32*)(smem + OV_Q);

    int qt = blockIdx.x, bh = blockIdx.y, ks = blockIdx.z;
    int b = bh >> 2, hh = bh & 3;
    const float* qb = g_qkv + (b * 120 + hh * 10) * SS;
    const float* kb = qb + 40 * SS + ks * 512;
    const float* vb = qb + 80 * SS + ks * 512;
    int tid = threadIdx.x;
    int lane = tid & 31, wz = tid >> 5;
    int g = lane >> 2, t = lane & 3;

    // phase A: srel + Q staging (overlay region)
    for (int i = tid; i < 1260; i += 256) srel[i] = (i < 630 ? relh[i] : relw[i - 630]);
    float qv[10];
    {
        int n = qt * 256 + tid;
#pragma unroll
        for (int d = 0; d < 10; d++) {
            qv[d] = qb[d * SS + n] * SCL;
            Qsm[tid * 16 + d] = __float2bfloat16(qv[d]);
        }
        Q32[tid * 8 + 5] = 0; Q32[tid * 8 + 6] = 0; Q32[tid * 8 + 7] = 0;
    }
    __syncthreads();

    // phase B: extract Q fragments; compute rel tables (RWP full 32 x', RH 16 y' of this split)
    uint32 qa[2][4];
#pragma unroll
    for (int mt = 0; mt < 2; mt++) {
        int r0 = wz * 32 + mt * 16;
        qa[mt][0] = Q32[(r0 + g) * 8 + t];
        qa[mt][1] = Q32[(r0 + g + 8) * 8 + t];
        qa[mt][2] = Q32[(r0 + g) * 8 + t + 4];
        qa[mt][3] = Q32[(r0 + g + 8) * 8 + t + 4];
    }
    {
        int n = qt * 256 + tid;
        int x = n & 31, y = n >> 5;
        float prev = 0.f;
        for (int t2 = 0; t2 < 32; t2++) {
            const float* pw = srel + 630 + (t2 - x + 31) * 10;
            float aw = 0.f;
#pragma unroll
            for (int d = 0; d < 10; d++) aw += qv[d] * pw[d];
            if (t2 & 1) RWP[tid * 17 + (t2 >> 1)] = pkbf(aw, prev);
            else prev = aw;
            if ((t2 >> 4) == ks) {
                const float* ph = srel + (t2 - y + 31) * 10;
                float ah = 0.f;
#pragma unroll
                for (int d = 0; d < 10; d++) ah += qv[d] * ph[d];
                RH[tid * 17 + (t2 & 15)] = __float2bfloat16(ah);
            }
        }
    }
    __syncthreads();

    // phase C: stage K, V over the overlay region
#pragma unroll
    for (int d = 0; d < 10; d++) {
        for (int m = tid; m < 512; m += 256)
            Ksm[m * 18 + d] = __float2bfloat16(kb[d * SS + m]);
        for (int i = tid; i < 256; i += 256) {
            float2 v = *(const float2*)(vb + d * SS + 2 * i);
            V32[d * 260 + i] = pkbf(v.y, v.x);
        }
    }
    for (int m = tid; m < 512; m += 256) {
        K32[m * 9 + 5] = 0; K32[m * 9 + 6] = 0; K32[m * 9 + 7] = 0; K32[m * 9 + 8] = 0;
    }
    for (int i = tid; i < 260; i += 256) V32[10 * 260 + i] = 0x3F803F80u;  // ones row
    for (int d = 11; d < 16; d++)
        for (int i = tid; i < 260; i += 256) V32[d * 260 + i] = 0;
    __syncthreads();

    // main loop: hf outer (rwv[2][8] live), my inner
    float O[2][2][4];
#pragma unroll
    for (int i = 0; i < 4; i++) {
        O[0][0][i] = 0.f; O[0][1][i] = 0.f; O[1][0][i] = 0.f; O[1][1][i] = 0.f;
    }

#pragma unroll
    for (int hf = 0; hf < 2; hf++) {
        float rwv[2][8];
#pragma unroll
        for (int mt = 0; mt < 2; mt++) {
            int r0 = wz * 32 + mt * 16 + g;
            int pi = hf * 8 + t;
            uint32 a0 = RWP[r0 * 17 + pi],       a1 = RWP[r0 * 17 + pi + 4];
            uint32 b0 = RWP[(r0 + 8) * 17 + pi], b1 = RWP[(r0 + 8) * 17 + pi + 4];
            rwv[mt][0] = lo_bf(a0); rwv[mt][1] = hi_bf(a0);
            rwv[mt][2] = lo_bf(a1); rwv[mt][3] = hi_bf(a1);
            rwv[mt][4] = lo_bf(b0); rwv[mt][5] = hi_bf(b0);
            rwv[mt][6] = lo_bf(b1); rwv[mt][7] = hi_bf(b1);
        }
        for (int my = 0; my < 16; my++) {
            int k0 = my * 32 + hf * 16;
            uint32 kb0[2], kb1[2], vb0[2], vb1[2];
            kb0[0] = K32[(k0 + g) * 9 + t];      kb0[1] = K32[(k0 + g) * 9 + t + 4];
            kb1[0] = K32[(k0 + 8 + g) * 9 + t];  kb1[1] = K32[(k0 + 8 + g) * 9 + t + 4];
            int kh = k0 >> 1;
            vb0[0] = V32[g * 260 + kh + t];        vb0[1] = V32[g * 260 + kh + t + 4];
            vb1[0] = V32[(g + 8) * 260 + kh + t];  vb1[1] = V32[(g + 8) * 260 + kh + t + 4];
            float c[2][2][4];
#pragma unroll
            for (int mt = 0; mt < 2; mt++) {
#pragma unroll
                for (int j = 0; j < 4; j++) { c[mt][0][j] = 0.f; c[mt][1][j] = 0.f; }
                MMA16(c[mt][0], qa[mt], kb0);
                MMA16(c[mt][1], qa[mt], kb1);
            }
#pragma unroll
            for (int mt = 0; mt < 2; mt++) {
                int r0 = wz * 32 + mt * 16 + g;
                float rh0 = __uint_as_float(((uint32)*(const unsigned short*)&RH[r0 * 17 + my]) << 16);
                float rh1 = __uint_as_float(((uint32)*(const unsigned short*)&RH[(r0 + 8) * 17 + my]) << 16);
                const float* rw = rwv[mt];
                float p00 = ex2f(c[mt][0][0] + (rw[0] + rh0));
                float p01 = ex2f(c[mt][0][1] + (rw[1] + rh0));
                float p02 = ex2f(c[mt][0][2] + (rw[4] + rh1));
                float p03 = ex2f(c[mt][0][3] + (rw[5] + rh1));
                float p10 = ex2f(c[mt][1][0] + (rw[2] + rh0));
                float p11 = ex2f(c[mt][1][1] + (rw[3] + rh0));
                float p12 = ex2f(c[mt][1][2] + (rw[6] + rh1));
                float p13 = ex2f(c[mt][1][3] + (rw[7] + rh1));
                uint32 pa[4];
                pa[0] = pkbf(p01, p00);
                pa[1] = pkbf(p03, p02);
                pa[2] = pkbf(p11, p10);
                pa[3] = pkbf(p13, p12);
                MMA16(O[mt][0], pa, vb0);
                MMA16(O[mt][1], pa, vb1);
            }
        }
    }

    // epilogue: store raw partials (O cols 0..9 + s at [10]); no normalization
#pragma unroll
    for (int mt = 0; mt < 2; mt++) {
        int q0 = qt * 256 + wz * 32 + mt * 16 + g;
        float* op = g_apart + ((size_t)(ks * 64 + bh) * 1024 + q0) * 12;
        *(float2*)(op + 2 * t)      = make_float2(O[mt][0][0], O[mt][0][1]);
        *(float2*)(op + 96 + 2 * t) = make_float2(O[mt][0][2], O[mt][0][3]);
        if (t == 0) {
            *(float2*)(op + 8)      = make_float2(O[mt][1][0], O[mt][1][1]);
            *(float2*)(op + 96 + 8) = make_float2(O[mt][1][2], O[mt][1][3]);
        }
        if (t == 1) {
            op[10]      = O[mt][1][0];   // ones-column = sum (cols 10)
            op[96 + 10] = O[mt][1][2];
        }
    }
}

// ---------------- combine split-K partials ----------------
__global__ void __launch_bounds__(256) combine_kernel() {
    int q = blockIdx.x * 256 + threadIdx.x;     // 0..65535
    const float4* p0 = (const float4*)(g_apart + (size_t)q * 12);
    const float4* p1 = (const float4*)(g_apart + (size_t)(65536 + q) * 12);
    float4 a0 = p0[0], a1 = p0[1], a2 = p0[2];
    float4 b0 = p1[0], b1 = p1[1], b2 = p1[2];
    float inv = 1.f / (a2.z + b2.z);
    float* o = g_attn + (size_t)q * 10;
    *(float2*)(o)     = make_float2((a0.x + b0.x) * inv, (a0.y + b0.y) * inv);
    *(float2*)(o + 2) = make_float2((a0.z + b0.z) * inv, (a0.w + b0.w) * inv);
    *(float2*)(o + 4) = make_float2((a1.x + b1.x) * inv, (a1.y + b1.y) * inv);
    *(float2*)(o + 6) = make_float2((a1.z + b1.z) * inv, (a1.w + b1.w) * inv);
    *(float2*)(o + 8) = make_float2((a2.x + b2.x) * inv, (a2.y + b2.y) * inv);
}

// ---------------- pool + attno(on pooled) + fc, fused ----------------
__global__ void __launch_bounds__(512) poolfc_kernel(
        const float* __restrict__ attw, const float* __restrict__ attb,
        const float* __restrict__ fcw, const float* __restrict__ fcb,
        float* __restrict__ out) {
    int b = blockIdx.x;
    int tid = threadIdx.x;
    int warp = tid >> 5, lane = tid & 31;
    __shared__ float pooled[128];
    __shared__ float pA[40];
#pragma unroll
    for (int i = 0; i < 8; i++) {
        int c = warp * 8 + i;
        const float* src = (c < CO) ? g_conv + (size_t)(b * CO + c) * SS
                                    : g_attn + (size_t)b * 40960 + (c - CO) * SS;
        const float4* p = (const float4*)src;
        float s = 0.f;
#pragma unroll
        for (int j = 0; j < 8; j++) {
            float4 v = p[j * 32 + lane];
            s += (v.x + v.y) + (v.z + v.w);
        }
#pragma unroll
        for (int o = 16; o; o >>= 1) s += __shfl_xor_sync(0xffffffffu, s, o);
        if (lane == 0) {
            if (c < CO) pooled[c] = s * (1.f / SS);
            else        pA[c - CO] = s * (1.f / SS);
        }
    }
    __syncthreads();
    if (tid < 40) {
        float a = attb[tid];
#pragma unroll 8
        for (int ic = 0; ic < 40; ic++) a += attw[tid * 40 + ic] * pA[ic];
        pooled[CO + tid] = a;
    }
    __syncthreads();
    if (tid < 100) {
        float a = fcb[tid];
#pragma unroll 8
        for (int c = 0; c < 128; c++) a += pooled[c] * fcw[tid * 128 + c];
        out[b * 100 + tid] = a;
    }
}

// ---------------- host ----------------
extern "C" void kernel_launch(void* const* d_in, const int* in_sizes, int n_in,
                              void* d_out, int out_size) {
    const float* x        = (const float*)d_in[0];
    const float* conv1_w  = (const float*)d_in[1];
    const float* conv1_b  = (const float*)d_in[2];
    const float* bn1_g    = (const float*)d_in[3];
    const float* bn1_b    = (const float*)d_in[4];
    const float* convo_w  = (const float*)d_in[5];
    const float* convo_b  = (const float*)d_in[6];
    const float* qkv_w    = (const float*)d_in[7];
    const float* qkv_b    = (const float*)d_in[8];
    const float* attno_w  = (const float*)d_in[9];
    const float* attno_b  = (const float*)d_in[10];
    const float* key_rel_h = (const float*)d_in[11];
    const float* key_rel_w = (const float*)d_in[12];
    const float* fc_w     = (const float*)d_in[13];
    const float* fc_b     = (const float*)d_in[14];
    float* out = (float*)d_out;

    static cudaStream_t s1 = nullptr;
    static cudaEvent_t evA = nullptr, evB = nullptr;
    if (!s1) {
        cudaStreamCreateWithFlags(&s1, cudaStreamNonBlocking);
        cudaEventCreateWithFlags(&evA, cudaEventDisableTiming);
        cudaEventCreateWithFlags(&evB, cudaEventDisableTiming);
    }

    cudaFuncSetAttribute(attn_kernel, cudaFuncAttributeMaxDynamicSharedMemorySize, ATTN_SMEM);
    cudaFuncSetAttribute(convo_mma_kernel, cudaFuncAttributeMaxDynamicSharedMemorySize, CONVO_SMEM);
    cudaFuncSetAttribute(qkv_mma_kernel, cudaFuncAttributeMaxDynamicSharedMemorySize, QKV_SMEM);

    conv1_kernel<<<dim3(64, BB), 256>>>(x, conv1_w, conv1_b, convo_w, qkv_w);

    cudaEventRecord(evA, 0);
    cudaStreamWaitEvent(s1, evA, 0);
    convo_mma_kernel<<<dim3(8, BB, 2), 256, CONVO_SMEM, s1>>>(convo_b, bn1_g, bn1_b);
    cudaEventRecord(evB, s1);

    qkv_mma_kernel<<<dim3(8, BB), 256, QKV_SMEM>>>(qkv_b, bn1_g, bn1_b);
    attn_kernel<<<dim3(4, 64, 2), 256, ATTN_SMEM>>>(key_rel_h, key_rel_w);
    combine_kernel<<<256, 256>>>();

    cudaStreamWaitEvent(0, evB, 0);
    poolfc_kernel<<<BB, 512>>>(attno_w, attno_b, fc_w, fc_b, out);
}

// round 16
// speedup vs baseline: 1.0712x; 1.0712x over previous
#include <cuda_runtime.h>
#include <cuda_bf16.h>

#define BB 16
#define SS 1024
#define CO 88
#define QSCALE 0.31622776601683794f
#define L2E 1.4426950408889634f
#define SCL (QSCALE * L2E)

typedef unsigned int uint32;

__device__ __forceinline__ float ex2f(float x) {
    float r; asm("ex2.approx.ftz.f32 %0, %1;" : "=f"(r) : "f"(x)); return r;
}
__device__ __forceinline__ uint32 pkbf(float hi, float lo) {
    uint32 r; asm("cvt.rn.bf16x2.f32 %0, %1, %2;" : "=r"(r) : "f"(hi), "f"(lo)); return r;
}
__device__ __forceinline__ uint32 f2tf(float x) {
    uint32 r; asm("cvt.rna.tf32.f32 %0, %1;" : "=r"(r) : "f"(x)); return r;
}
__device__ __forceinline__ float lo_bf(uint32 p) { return __uint_as_float(p << 16); }
__device__ __forceinline__ float hi_bf(uint32 p) { return __uint_as_float(p & 0xffff0000u); }
#define MMA16(d, a, b) asm volatile( \
    "mma.sync.aligned.m16n8k16.row.col.f32.bf16.bf16.f32 " \
    "{%0,%1,%2,%3}, {%4,%5,%6,%7}, {%8,%9}, {%0,%1,%2,%3};\n" \
    : "+f"(d[0]), "+f"(d[1]), "+f"(d[2]), "+f"(d[3]) \
    : "r"(a[0]), "r"(a[1]), "r"(a[2]), "r"(a[3]), "r"(b[0]), "r"(b[1]))
#define MMAT(d, a, b) asm volatile( \
    "mma.sync.aligned.m16n8k8.row.col.f32.tf32.tf32.f32 " \
    "{%0,%1,%2,%3}, {%4,%5,%6,%7}, {%8,%9}, {%0,%1,%2,%3};\n" \
    : "+f"(d[0]), "+f"(d[1]), "+f"(d[2]), "+f"(d[3]) \
    : "r"(a[0]), "r"(a[1]), "r"(a[2]), "r"(a[3]), "r"(b[0]), "r"(b[1]))

// ---------------- scratch ----------------
__device__ float g_h[BB * 64 * SS];
__device__ float g_part[BB * 64 * 2];
__device__ float g_conv[BB * CO * SS];
__device__ float g_qkv[BB * 120 * SS];
__device__ float g_attn[BB * 4 * SS * 10];
__device__ uint32 g_wco[4 * 9 * 88 * 16];   // tf32 bits: [icc][kk][oc][ic]
__device__ uint32 g_wq[120 * 64];           // tf32 bits: [oc][ic]

// ---------------- BN scale/shift recompute (inline per block) ----------------
__device__ __forceinline__ void bn_inline(float* bns, float* bnb,
                                          const float* __restrict__ gma,
                                          const float* __restrict__ bet, int tid) {
    if (tid < 64) {
        float S = 0.f, S2 = 0.f;
#pragma unroll
        for (int ib = 0; ib < 16; ib++) {
            S  += g_part[(ib * 64 + tid) * 2];
            S2 += g_part[(ib * 64 + tid) * 2 + 1];
        }
        float mu  = S * (1.f / 16384.f);
        float var = S2 * (1.f / 16384.f) - mu * mu;
        float sc = gma[tid] * rsqrtf(var + 1e-5f);
        bns[tid] = sc;
        bnb[tid] = bet[tid] - mu * sc;
    }
}

// ---------------- conv1 3->64 3x3 + BN partial stats + weight prep ----------------
__global__ void conv1_kernel(const float* __restrict__ x, const float* __restrict__ w,
                             const float* __restrict__ bias,
                             const float* __restrict__ convo_w,
                             const float* __restrict__ qkv_w) {
    int oc = blockIdx.x, b = blockIdx.y;
    __shared__ float xs[3 * 34 * 34];
    __shared__ float ws[27];
    __shared__ float sred[16];
    int tid = threadIdx.x;
    if (b == 0) {
        int base = oc * 256 + tid;
        for (int i = base; i < 4 * 9 * 88 * 16; i += 16384) {
            int ic16 = i & 15, r = i >> 4;
            int occ = r % 88; r /= 88;
            int kk = r % 9;  int icc = r / 9;
            g_wco[i] = f2tf(convo_w[(occ * 64 + icc * 16 + ic16) * 9 + kk]);
        }
        for (int i = base; i < 120 * 64; i += 16384) g_wq[i] = f2tf(qkv_w[i]);
    }
    for (int i = tid; i < 3 * 1156; i += 256) {
        int ic = i / 1156, r = i % 1156;
        int y = r / 34 - 1, xx = r % 34 - 1;
        float v = 0.f;
        if ((unsigned)y < 32u && (unsigned)xx < 32u)
            v = x[(b * 3 + ic) * SS + y * 32 + xx];
        xs[i] = v;
    }
    if (tid < 27) ws[tid] = w[oc * 27 + tid];
    __syncthreads();
    float bb = bias[oc];
    float s = 0.f, s2 = 0.f;
    for (int p = tid; p < SS; p += 256) {
        int y = p >> 5, xx = p & 31;
        float acc = bb;
#pragma unroll
        for (int ic = 0; ic < 3; ic++)
#pragma unroll
            for (int ky = 0; ky < 3; ky++)
#pragma unroll
                for (int kx = 0; kx < 3; kx++)
                    acc += xs[ic * 1156 + (y + ky) * 34 + xx + kx] * ws[ic * 9 + ky * 3 + kx];
        g_h[(b * 64 + oc) * SS + p] = acc;
        s += acc; s2 += acc * acc;
    }
#pragma unroll
    for (int o = 16; o; o >>= 1) {
        s  += __shfl_xor_sync(0xffffffffu, s, o);
        s2 += __shfl_xor_sync(0xffffffffu, s2, o);
    }
    if ((tid & 31) == 0) { sred[tid >> 5] = s; sred[8 + (tid >> 5)] = s2; }
    __syncthreads();
    if (tid == 0) {
        float S = 0.f, S2 = 0.f;
        for (int i = 0; i < 8; i++) { S += sred[i]; S2 += sred[8 + i]; }
        g_part[(b * 64 + oc) * 2]     = S;
        g_part[(b * 64 + oc) * 2 + 1] = S2;
    }
}

// ---------------- convo: tf32 implicit-GEMM, oc-split (48 + 40) ----------------
#define CONVO_SMEM ((6 * 36 * 18 + 9 * 48 * 18 + 48) * 4)
template <int NT, int OCB>
__device__ __forceinline__ void convo_impl(const float* __restrict__ bias,
                                           const float* __restrict__ gma,
                                           const float* __restrict__ bet) {
    extern __shared__ uint32 dynu[];
    uint32* xs = dynu;
    uint32* ws = xs + 6 * 36 * 18;
    float* bsm = (float*)(ws + 9 * 48 * 18);
    __shared__ float bns[64], bnb[64];
    int pxt = blockIdx.x, b = blockIdx.y;
    int y0 = pxt * 4;
    int tid = threadIdx.x;
    int wz = tid >> 5, lane = tid & 31;
    int g = lane >> 2, t = lane & 3;
    int wrow = wz >> 1, mtx = (wz & 1) * 16;

    bn_inline(bns, bnb, gma, bet, tid);
    if (tid < NT * 8) bsm[tid] = bias[OCB + tid];

    float acc[NT][4];
#pragma unroll
    for (int n = 0; n < NT; n++)
#pragma unroll
        for (int j = 0; j < 4; j++) acc[n][j] = 0.f;

    for (int icc = 0; icc < 4; icc++) {
        __syncthreads();
        for (int i = tid; i < 3456; i += 256) {
            int ic = i / 216, rem = i % 216;
            int row = rem / 36, col = rem % 36;
            int iy = y0 - 1 + row, ix = col - 1;
            float v = 0.f;
            int icg = icc * 16 + ic;
            if ((unsigned)iy < 32u && (unsigned)ix < 32u) {
                v = g_h[(b * 64 + icg) * SS + iy * 32 + ix];
                v = fmaxf(v * bns[icg] + bnb[icg], 0.f);
            }
            xs[(row * 36 + col) * 18 + ic] = f2tf(v);
        }
        for (int i = tid; i < 9 * NT * 8 * 16; i += 256) {
            int ic = i & 15, m = i >> 4;
            int ocl = m % (NT * 8), kk = m / (NT * 8);
            ws[(kk * 48 + ocl) * 18 + ic] = g_wco[((icc * 9 + kk) * 88 + OCB + ocl) * 16 + ic];
        }
        __syncthreads();
#pragma unroll
        for (int kk = 0; kk < 9; kk++) {
            int ky = kk / 3, kx = kk % 3;
            const uint32* xrow = xs + ((wrow + ky) * 36 + mtx + kx) * 18;
            const uint32* wrow_p = ws + kk * 48 * 18;
#pragma unroll
            for (int j = 0; j < 2; j++) {
                uint32 a[4];
                a[0] = xrow[g * 18 + 8 * j + t];
                a[1] = xrow[(g + 8) * 18 + 8 * j + t];
                a[2] = xrow[g * 18 + 8 * j + t + 4];
                a[3] = xrow[(g + 8) * 18 + 8 * j + t + 4];
#pragma unroll
                for (int nt = 0; nt < NT; nt++) {
                    uint32 bfrag[2];
                    bfrag[0] = wrow_p[(nt * 8 + g) * 18 + 8 * j + t];
                    bfrag[1] = wrow_p[(nt * 8 + g) * 18 + 8 * j + t + 4];
                    MMAT(acc[nt], a, bfrag);
                }
            }
        }
    }
    int pxbase = (y0 + wrow) * 32 + mtx;
#pragma unroll
    for (int nt = 0; nt < NT; nt++) {
        int oc0 = OCB + nt * 8 + 2 * t;
        float b0 = bsm[nt * 8 + 2 * t], b1 = bsm[nt * 8 + 2 * t + 1];
        float* o0 = g_conv + (size_t)(b * 88 + oc0) * SS + pxbase;
        float* o1 = o0 + SS;
        o0[g]     = acc[nt][0] + b0;
        o1[g]     = acc[nt][1] + b1;
        o0[g + 8] = acc[nt][2] + b0;
        o1[g + 8] = acc[nt][3] + b1;
    }
}

__global__ void __launch_bounds__(256) convo_mma_kernel(const float* __restrict__ bias,
                                                        const float* __restrict__ gma,
                                                        const float* __restrict__ bet) {
    if (blockIdx.z == 0) convo_impl<6, 0>(bias, gma, bet);
    else                 convo_impl<5, 48>(bias, gma, bet);
}

// ---------------- qkv 1x1: tf32 MMA GEMM ----------------
#define QKV_SMEM ((128 * 68 + 120 * 68 + 120) * 4)
__global__ void __launch_bounds__(256) qkv_mma_kernel(const float* __restrict__ bias,
                                                      const float* __restrict__ gma,
                                                      const float* __restrict__ bet) {
    extern __shared__ uint32 dynu[];
    uint32* As = dynu;
    uint32* wqs = As + 128 * 68;
    float* bsm = (float*)(wqs + 120 * 68);
    __shared__ float bns[64], bnb[64];
    int pxt = blockIdx.x, b = blockIdx.y;
    int p0 = pxt * 128;
    int tid = threadIdx.x;
    int wz = tid >> 5, lane = tid & 31;
    int g = lane >> 2, t = lane & 3;

    bn_inline(bns, bnb, gma, bet, tid);
    for (int i = tid; i < 120; i += 256) bsm[i] = bias[i];
    for (int i = tid; i < 120 * 64; i += 256) {
        int n = i >> 6, ic = i & 63;
        wqs[n * 68 + ic] = g_wq[i];
    }
    __syncthreads();
    for (int i = tid; i < 128 * 64; i += 256) {
        int ic = i >> 7, px = i & 127;
        float v = g_h[(b * 64 + ic) * SS + p0 + px];
        v = fmaxf(v * bns[ic] + bnb[ic], 0.f);
        As[px * 68 + ic] = f2tf(v);
    }
    __syncthreads();

    float acc[15][4];
#pragma unroll
    for (int n = 0; n < 15; n++)
#pragma unroll
        for (int j = 0; j < 4; j++) acc[n][j] = 0.f;

#pragma unroll
    for (int kc = 0; kc < 8; kc++) {
        int ic0 = kc * 8;
        const uint32* ar = As + (wz * 16) * 68 + ic0;
        uint32 a[4];
        a[0] = ar[g * 68 + t];
        a[1] = ar[(g + 8) * 68 + t];
        a[2] = ar[g * 68 + t + 4];
        a[3] = ar[(g + 8) * 68 + t + 4];
#pragma unroll
        for (int nt = 0; nt < 15; nt++) {
            uint32 bfrag[2];
            bfrag[0] = wqs[(nt * 8 + g) * 68 + ic0 + t];
            bfrag[1] = wqs[(nt * 8 + g) * 68 + ic0 + t + 4];
            MMAT(acc[nt], a, bfrag);
        }
    }
    int pxb = p0 + wz * 16;
#pragma unroll
    for (int nt = 0; nt < 15; nt++) {
        int oc0 = nt * 8 + 2 * t;
        float b0 = bsm[oc0], b1 = bsm[oc0 + 1];
        float* o0 = g_qkv + (size_t)(b * 120 + oc0) * SS + pxb;
        float* o1 = o0 + SS;
        o0[g]     = acc[nt][0] + b0;
        o1[g]     = acc[nt][1] + b1;
        o0[g + 8] = acc[nt][2] + b0;
        o1[g + 8] = acc[nt][3] + b1;
    }
}

// ---------------- fused attention: full-K, software-pipelined QK/epilogue ----------------
#define SM_K   0                       // 1024*9 uint (bf16 rows stride 18)
#define SM_V   36864                   // 16*516 uint
#define SM_Q   69888                   // 256*8 uint (later: srel f32[1260])
#define SM_RW  78080                   // 256*17 uint (bf16x2 pairs)
#define SM_RH  95488                   // 256*33 bf16
#define ATTN_SMEM 112384

__global__ void __launch_bounds__(256, 2) attn_kernel(const float* __restrict__ relh,
                                                      const float* __restrict__ relw) {
    extern __shared__ char smem[];
    __nv_bfloat16* Ksm = (__nv_bfloat16*)(smem + SM_K);   // [1024][18]
    __nv_bfloat16* Qsm = (__nv_bfloat16*)(smem + SM_Q);   // [256][16]
    uint32* K32 = (uint32*)(smem + SM_K);
    uint32* V32 = (uint32*)(smem + SM_V);                 // [16][516]
    uint32* Q32 = (uint32*)(smem + SM_Q);
    uint32* RWP = (uint32*)(smem + SM_RW);                // [256][17] bf16x2 pairs
    __nv_bfloat16* RH = (__nv_bfloat16*)(smem + SM_RH);   // [256][33]

    int qt = blockIdx.x, bh = blockIdx.y;
    int b = bh >> 2, hh = bh & 3;
    const float* qb = g_qkv + (b * 120 + hh * 10) * SS;
    const float* kb = qb + 40 * SS;
    const float* vb = qb + 80 * SS;
    int tid = threadIdx.x;
    int lane = tid & 31, wz = tid >> 5;
    int g = lane >> 2, t = lane & 3;

    // phase 1: stage K, V (row 10 = ones for softmax-sum), Q
#pragma unroll
    for (int d = 0; d < 10; d++)
        for (int m = tid; m < 1024; m += 256)
            Ksm[m * 18 + d] = __float2bfloat16(kb[d * SS + m]);
    for (int m = tid; m < 1024; m += 256) {
        K32[m * 9 + 5] = 0; K32[m * 9 + 6] = 0; K32[m * 9 + 7] = 0; K32[m * 9 + 8] = 0;
    }
#pragma unroll
    for (int d = 0; d < 10; d++)
        for (int i = tid; i < 512; i += 256) {
            float2 v = *(const float2*)(vb + d * SS + 2 * i);
            V32[d * 516 + i] = pkbf(v.y, v.x);
        }
    for (int i = tid; i < 516; i += 256) V32[10 * 516 + i] = 0x3F803F80u;  // ones row
    for (int d = 11; d < 16; d++)
        for (int i = tid; i < 516; i += 256) V32[d * 516 + i] = 0;
    float qv[10];
    {
        int n = qt * 256 + tid;
#pragma unroll
        for (int d = 0; d < 10; d++) {
            qv[d] = qb[d * SS + n] * SCL;
            Qsm[tid * 16 + d] = __float2bfloat16(qv[d]);
        }
        Q32[tid * 8 + 5] = 0; Q32[tid * 8 + 6] = 0; Q32[tid * 8 + 7] = 0;
    }
    __syncthreads();

    // phase 2: extract Q fragments
    uint32 qa[2][4];
#pragma unroll
    for (int mt = 0; mt < 2; mt++) {
        int r0 = wz * 32 + mt * 16;
        qa[mt][0] = Q32[(r0 + g) * 8 + t];
        qa[mt][1] = Q32[(r0 + g + 8) * 8 + t];
        qa[mt][2] = Q32[(r0 + g) * 8 + t + 4];
        qa[mt][3] = Q32[(r0 + g + 8) * 8 + t + 4];
    }
    __syncthreads();

    // phase 3: srel into dead Q region
    float* srel = (float*)(smem + SM_Q);
    for (int i = tid; i < 1260; i += 256) srel[i] = (i < 630 ? relh[i] : relw[i - 630]);
    __syncthreads();

    // phase 4: rel tables
    {
        int n = qt * 256 + tid;
        int x = n & 31, y = n >> 5;
        float prev = 0.f;
        for (int t2 = 0; t2 < 32; t2++) {
            const float* pw = srel + 630 + (t2 - x + 31) * 10;
            const float* ph = srel + (t2 - y + 31) * 10;
            float aw = 0.f, ah = 0.f;
#pragma unroll
            for (int d = 0; d < 10; d++) { aw += qv[d] * pw[d]; ah += qv[d] * ph[d]; }
            RH[tid * 33 + t2] = __float2bfloat16(ah);
            if (t2 & 1) RWP[tid * 17 + (t2 >> 1)] = pkbf(aw, prev);
            else prev = aw;
        }
    }
    __syncthreads();

    // phase 5: hoist rel-width logits into registers
    float rwv[2][2][8];
#pragma unroll
    for (int mt = 0; mt < 2; mt++) {
        int r0 = wz * 32 + mt * 16 + g;
#pragma unroll
        for (int hf = 0; hf < 2; hf++) {
            int pi = hf * 8 + t;
            uint32 a0 = RWP[r0 * 17 + pi],       a1 = RWP[r0 * 17 + pi + 4];
            uint32 b0 = RWP[(r0 + 8) * 17 + pi], b1 = RWP[(r0 + 8) * 17 + pi + 4];
            rwv[mt][hf][0] = lo_bf(a0); rwv[mt][hf][1] = hi_bf(a0);
            rwv[mt][hf][2] = lo_bf(a1); rwv[mt][hf][3] = hi_bf(a1);
            rwv[mt][hf][4] = lo_bf(b0); rwv[mt][hf][5] = hi_bf(b0);
            rwv[mt][hf][6] = lo_bf(b1); rwv[mt][hf][7] = hi_bf(b1);
        }
    }

    float O[2][2][4];
#pragma unroll
    for (int i = 0; i < 4; i++) {
        O[0][0][i] = 0.f; O[0][1][i] = 0.f; O[1][0][i] = 0.f; O[1][1][i] = 0.f;
    }

    // ---- software-pipelined main loop: QK(ch+1) issued before epilogue(ch) ----
#define QK_STAGE(CH, C, VB0, VB1) do { \
        int k0_ = ((CH) >> 1) * 32 + (((CH) & 1) << 4); \
        uint32 kb0_[2], kb1_[2]; \
        kb0_[0] = K32[(k0_ + g) * 9 + t];      kb0_[1] = K32[(k0_ + g) * 9 + t + 4]; \
        kb1_[0] = K32[(k0_ + 8 + g) * 9 + t];  kb1_[1] = K32[(k0_ + 8 + g) * 9 + t + 4]; \
        int kh_ = k0_ >> 1; \
        VB0[0] = V32[g * 516 + kh_ + t];        VB0[1] = V32[g * 516 + kh_ + t + 4]; \
        VB1[0] = V32[(g + 8) * 516 + kh_ + t];  VB1[1] = V32[(g + 8) * 516 + kh_ + t + 4]; \
        _Pragma("unroll") \
        for (int mt_ = 0; mt_ < 2; mt_++) { \
            _Pragma("unroll") \
            for (int j_ = 0; j_ < 4; j_++) { C[mt_][0][j_] = 0.f; C[mt_][1][j_] = 0.f; } \
            MMA16(C[mt_][0], qa[mt_], kb0_); \
            MMA16(C[mt_][1], qa[mt_], kb1_); \
        } \
    } while (0)

#define EPI_STAGE(CH, C, VB0, VB1) do { \
        int my_ = (CH) >> 1, hf_ = (CH) & 1; \
        _Pragma("unroll") \
        for (int mt_ = 0; mt_ < 2; mt_++) { \
            int r0_ = wz * 32 + mt_ * 16 + g; \
            float rh0_ = __uint_as_float(((uint32)*(const unsigned short*)&RH[r0_ * 33 + my_]) << 16); \
            float rh1_ = __uint_as_float(((uint32)*(const unsigned short*)&RH[(r0_ + 8) * 33 + my_]) << 16); \
            const float* rw_ = rwv[mt_][hf_]; \
            float p00 = ex2f(C[mt_][0][0] + (rw_[0] + rh0_)); \
            float p01 = ex2f(C[mt_][0][1] + (rw_[1] + rh0_)); \
            float p02 = ex2f(C[mt_][0][2] + (rw_[4] + rh1_)); \
            float p03 = ex2f(C[mt_][0][3] + (rw_[5] + rh1_)); \
            float p10 = ex2f(C[mt_][1][0] + (rw_[2] + rh0_)); \
            float p11 = ex2f(C[mt_][1][1] + (rw_[3] + rh0_)); \
            float p12 = ex2f(C[mt_][1][2] + (rw_[6] + rh1_)); \
            float p13 = ex2f(C[mt_][1][3] + (rw_[7] + rh1_)); \
            uint32 pa_[4]; \
            pa_[0] = pkbf(p01, p00); \
            pa_[1] = pkbf(p03, p02); \
            pa_[2] = pkbf(p11, p10); \
            pa_[3] = pkbf(p13, p12); \
            MMA16(O[mt_][0], pa_, VB0); \
            MMA16(O[mt_][1], pa_, VB1); \
        } \
    } while (0)

    {
        float cA[2][2][4], cB[2][2][4];
        uint32 vA0[2], vA1[2], vB0[2], vB1[2];
        QK_STAGE(0, cA, vA0, vA1);
#pragma unroll 1
        for (int ch = 0; ch < 64; ch += 2) {
            QK_STAGE(ch + 1, cB, vB0, vB1);
            EPI_STAGE(ch, cA, vA0, vA1);
            if (ch < 62) QK_STAGE(ch + 2, cA, vA0, vA1);
            EPI_STAGE(ch + 1, cB, vB0, vB1);
        }
    }

    // epilogue: softmax sums live in V-ones column (col 10, t==1 lanes)
#pragma unroll
    for (int mt = 0; mt < 2; mt++) {
        int src = (lane & 28) | 1;
        float s0 = __shfl_sync(0xffffffffu, O[mt][1][0], src);
        float s1 = __shfl_sync(0xffffffffu, O[mt][1][2], src);
        float i0 = 1.f / s0, i1 = 1.f / s1;
        int q0 = qt * 256 + wz * 32 + mt * 16 + g;
        float* op = g_attn + ((size_t)bh * 1024 + q0) * 10;
        *(float2*)(op + 2 * t)      = make_float2(O[mt][0][0] * i0, O[mt][0][1] * i0);
        *(float2*)(op + 80 + 2 * t) = make_float2(O[mt][0][2] * i1, O[mt][0][3] * i1);
        if (t == 0) {
            *(float2*)(op + 8)      = make_float2(O[mt][1][0] * i0, O[mt][1][1] * i0);
            *(float2*)(op + 80 + 8) = make_float2(O[mt][1][2] * i1, O[mt][1][3] * i1);
        }
    }
}

// ---------------- pool + attno(on pooled) + fc, fused ----------------
__global__ void __launch_bounds__(512) poolfc_kernel(
        const float* __restrict__ attw, const float* __restrict__ attb,
        const float* __restrict__ fcw, const float* __restrict__ fcb,
        float* __restrict__ out) {
    int b = blockIdx.x;
    int tid = threadIdx.x;
    int warp = tid >> 5, lane = tid & 31;
    __shared__ float pooled[128];
    __shared__ float pA[40];
#pragma unroll
    for (int i = 0; i < 8; i++) {
        int c = warp * 8 + i;
        const float* src = (c < CO) ? g_conv + (size_t)(b * CO + c) * SS
                                    : g_attn + (size_t)b * 40960 + (c - CO) * SS;
        const float4* p = (const float4*)src;
        float s = 0.f;
#pragma unroll
        for (int j = 0; j < 8; j++) {
            float4 v = p[j * 32 + lane];
            s += (v.x + v.y) + (v.z + v.w);
        }
#pragma unroll
        for (int o = 16; o; o >>= 1) s += __shfl_xor_sync(0xffffffffu, s, o);
        if (lane == 0) {
            if (c < CO) pooled[c] = s * (1.f / SS);
            else        pA[c - CO] = s * (1.f / SS);
        }
    }
    __syncthreads();
    if (tid < 40) {
        float a = attb[tid];
#pragma unroll 8
        for (int ic = 0; ic < 40; ic++) a += attw[tid * 40 + ic] * pA[ic];
        pooled[CO + tid] = a;
    }
    __syncthreads();
    if (tid < 100) {
        float a = fcb[tid];
#pragma unroll 8
        for (int c = 0; c < 128; c++) a += pooled[c] * fcw[tid * 128 + c];
        out[b * 100 + tid] = a;
    }
}

// ---------------- host ----------------
extern "C" void kernel_launch(void* const* d_in, const int* in_sizes, int n_in,
                              void* d_out, int out_size) {
    const float* x        = (const float*)d_in[0];
    const float* conv1_w  = (const float*)d_in[1];
    const float* conv1_b  = (const float*)d_in[2];
    const float* bn1_g    = (const float*)d_in[3];
    const float* bn1_b    = (const float*)d_in[4];
    const float* convo_w  = (const float*)d_in[5];
    const float* convo_b  = (const float*)d_in[6];
    const float* qkv_w    = (const float*)d_in[7];
    const float* qkv_b    = (const float*)d_in[8];
    const float* attno_w  = (const float*)d_in[9];
    const float* attno_b  = (const float*)d_in[10];
    const float* key_rel_h = (const float*)d_in[11];
    const float* key_rel_w = (const float*)d_in[12];
    const float* fc_w     = (const float*)d_in[13];
    const float* fc_b     = (const float*)d_in[14];
    float* out = (float*)d_out;

    static cudaStream_t s1 = nullptr;
    static cudaEvent_t evA = nullptr, evB = nullptr;
    if (!s1) {
        cudaStreamCreateWithFlags(&s1, cudaStreamNonBlocking);
        cudaEventCreateWithFlags(&evA, cudaEventDisableTiming);
        cudaEventCreateWithFlags(&evB, cudaEventDisableTiming);
    }

    cudaFuncSetAttribute(attn_kernel, cudaFuncAttributeMaxDynamicSharedMemorySize, ATTN_SMEM);
    cudaFuncSetAttribute(convo_mma_kernel, cudaFuncAttributeMaxDynamicSharedMemorySize, CONVO_SMEM);
    cudaFuncSetAttribute(qkv_mma_kernel, cudaFuncAttributeMaxDynamicSharedMemorySize, QKV_SMEM);

    conv1_kernel<<<dim3(64, BB), 256>>>(x, conv1_w, conv1_b, convo_w, qkv_w);

    cudaEventRecord(evA, 0);
    cudaStreamWaitEvent(s1, evA, 0);
    convo_mma_kernel<<<dim3(8, BB, 2), 256, CONVO_SMEM, s1>>>(convo_b, bn1_g, bn1_b);
    cudaEventRecord(evB, s1);

    qkv_mma_kernel<<<dim3(8, BB), 256, QKV_SMEM>>>(qkv_b, bn1_g, bn1_b);
    attn_kernel<<<dim3(4, 64), 256, ATTN_SMEM>>>(key_rel_h, key_rel_w);

    cudaStreamWaitEvent(0, evB, 0);
    poolfc_kernel<<<BB, 512>>>(attno_w, attno_b, fc_w, fc_b, out);
}